// round 1
// baseline (speedup 1.0000x reference)
#include <cuda_runtime.h>
#include <math.h>

#define BB 8
#define TT 32
#define NN 1024
#define DIN 64
#define DR 128
#define DT_VAL 0.25f
#define KC 32

// ---------------- device scratch (no allocs allowed) ----------------
__device__ float g_h  [BB * NN * DR];   // recurrent state
__device__ float g_hv1[BB * NN * DR];   // pre-GRU state (goes to output head)
__device__ float g_u  [BB * NN * DR];   // ODE hidden
__device__ float g_P  [BB * NN * 256];  // projection buffer (ldP up to 256)
__device__ float g_z  [BB * NN * DR];
__device__ float g_r  [BB * NN * DR];
__device__ float g_obs[BB * TT];

// ---------------- init h = broadcast(h0) ----------------
__global__ void init_h_kernel(const float* __restrict__ h0) {
    int idx = blockIdx.x * blockDim.x + threadIdx.x;
    const int total = BB * NN * DR;
    for (; idx < total; idx += gridDim.x * blockDim.x)
        g_h[idx] = h0[idx & (DR - 1)];
}

// ---------------- obs[b,t] = (sum |mask| > 1e-4) ----------------
__global__ void obs_kernel(const float* __restrict__ masks) {
    int bt = blockIdx.x;                     // b*TT + t
    const float* m = masks + (size_t)bt * NN * DIN;
    float s = 0.f;
    for (int i = threadIdx.x; i < NN * DIN / 4; i += blockDim.x) {
        float4 v = ((const float4*)m)[i];
        s += fabsf(v.x) + fabsf(v.y) + fabsf(v.z) + fabsf(v.w);
    }
    __shared__ float red[256];
    red[threadIdx.x] = s;
    __syncthreads();
    for (int o = 128; o > 0; o >>= 1) {
        if (threadIdx.x < o) red[threadIdx.x] += red[threadIdx.x + o];
        __syncthreads();
    }
    if (threadIdx.x == 0) g_obs[bt] = (red[0] > 1e-4f) ? 1.f : 0.f;
}

// ---------------- projection: P = [x | h or r*h] @ W ----------------
// Block: 64 rows x 128 cols, 256 threads, 4x8 micro-tile, K-chunks of 32.
template<bool HAS_X, bool HAS_R>
__global__ __launch_bounds__(256) void proj_kernel(
    const float* __restrict__ xv, const float* __restrict__ xm, int t,
    const float* __restrict__ h,  const float* __restrict__ rr,
    const float* __restrict__ W,  int ldW,
    float* __restrict__ P, int ldP, int colOffP, int Ktot)
{
    __shared__ float Xs[KC][68];    // transposed: Xs[kk][row]
    __shared__ float Ws[KC][132];

    int rowTile = blockIdx.x * 64;
    int b  = rowTile >> 10;
    int i0 = rowTile & (NN - 1);
    int tid = threadIdx.x;
    int tx = tid & 15, ty = tid >> 4;
    int c0 = tx * 8,   r0 = ty * 4;

    const int Kx = HAS_X ? DIN : 0;
    const float* hb  = h + ((size_t)b * NN + i0) * DR;
    const float* rb  = HAS_R ? rr + ((size_t)b * NN + i0) * DR : nullptr;
    const float* xvb = HAS_X ? xv + (((size_t)b * TT + t) * NN + i0) * DIN : nullptr;
    const float* xmb = HAS_X ? xm + (((size_t)b * TT + t) * NN + i0) * DIN : nullptr;

    float acc[4][8];
    #pragma unroll
    for (int i = 0; i < 4; i++)
        #pragma unroll
        for (int j = 0; j < 8; j++) acc[i][j] = 0.f;

    for (int k0 = 0; k0 < Ktot; k0 += KC) {
        // input tile 64 x 32, stored transposed
        #pragma unroll
        for (int l = 0; l < 2; l++) {
            int idx = tid + l * 256;
            int r = idx >> 3, k4 = idx & 7;
            float4 v;
            if (HAS_X && k0 < DIN) {
                v = *(const float4*)(xvb + (size_t)r * DIN + k0 + k4 * 4);
                float4 mv = *(const float4*)(xmb + (size_t)r * DIN + k0 + k4 * 4);
                v.x *= mv.x; v.y *= mv.y; v.z *= mv.z; v.w *= mv.w;
            } else {
                int kh = k0 - Kx;
                v = *(const float4*)(hb + (size_t)r * DR + kh + k4 * 4);
                if (HAS_R) {
                    float4 rv = *(const float4*)(rb + (size_t)r * DR + kh + k4 * 4);
                    v.x *= rv.x; v.y *= rv.y; v.z *= rv.z; v.w *= rv.w;
                }
            }
            Xs[k4 * 4 + 0][r] = v.x;
            Xs[k4 * 4 + 1][r] = v.y;
            Xs[k4 * 4 + 2][r] = v.z;
            Xs[k4 * 4 + 3][r] = v.w;
        }
        // W tile 32 x 128
        #pragma unroll
        for (int l = 0; l < 4; l++) {
            int idx = tid + l * 256;
            int kk = idx >> 5, c4 = idx & 31;
            *(float4*)&Ws[kk][c4 * 4] =
                *(const float4*)(W + (size_t)(k0 + kk) * ldW + c4 * 4);
        }
        __syncthreads();
        #pragma unroll
        for (int kk = 0; kk < KC; kk++) {
            float4 av = *(float4*)&Xs[kk][r0];
            float a[4] = {av.x, av.y, av.z, av.w};
            float p[8];
            *(float4*)&p[0] = *(float4*)&Ws[kk][c0];
            *(float4*)&p[4] = *(float4*)&Ws[kk][c0 + 4];
            #pragma unroll
            for (int i = 0; i < 4; i++)
                #pragma unroll
                for (int j = 0; j < 8; j++)
                    acc[i][j] = fmaf(a[i], p[j], acc[i][j]);
        }
        __syncthreads();
    }
    float* Pb = P + ((size_t)b * NN + i0) * ldP + colOffP;
    #pragma unroll
    for (int i = 0; i < 4; i++) {
        float* pr = Pb + (size_t)(r0 + i) * ldP + c0;
        *(float4*)(pr + 0) = make_float4(acc[i][0], acc[i][1], acc[i][2], acc[i][3]);
        *(float4*)(pr + 4) = make_float4(acc[i][4], acc[i][5], acc[i][6], acc[i][7]);
    }
}

// ---------------- A-multiply with fused epilogue ----------------
// G[b,i,c] = sum_j A[b,i,j] * P[b,j,c]; MODE: 0 tanh->dst, 1 hv1=h+G*dt,
// 2 sigmoid (grid.y selects z/r), 3 GRU final blend.
template<int MODE>
__global__ __launch_bounds__(256) void amult_kernel(
    const float* __restrict__ A,
    const float* __restrict__ P, int ldP,
    const float* __restrict__ bias0, const float* __restrict__ bias1,
    float* __restrict__ dst0, float* __restrict__ dst1,
    const float* __restrict__ hsrc,
    const float* __restrict__ zsrc,
    const float* __restrict__ obsArr, int tIdx)
{
    __shared__ float As[KC][68];    // transposed: As[kk][row]
    __shared__ float Ps[KC][132];

    int b = blockIdx.z;
    int rowTile = blockIdx.x * 64;
    int cb = blockIdx.y;
    int colOff = cb * 128;

    const float* bias = (MODE == 2 && cb == 1) ? bias1 : bias0;
    float* dst        = (MODE == 2 && cb == 1) ? dst1  : dst0;

    int tid = threadIdx.x;
    int tx = tid & 15, ty = tid >> 4;
    int c0 = tx * 8,   r0 = ty * 4;

    const float* Ab = A + (size_t)b * NN * NN + (size_t)rowTile * NN;
    const float* Pb = P + (size_t)b * NN * ldP + colOff;

    float acc[4][8];
    #pragma unroll
    for (int i = 0; i < 4; i++)
        #pragma unroll
        for (int j = 0; j < 8; j++) acc[i][j] = 0.f;

    for (int k0 = 0; k0 < NN; k0 += KC) {
        #pragma unroll
        for (int l = 0; l < 2; l++) {
            int idx = tid + l * 256;
            int r = idx >> 3, k4 = idx & 7;
            float4 v = *(const float4*)(Ab + (size_t)r * NN + k0 + k4 * 4);
            As[k4 * 4 + 0][r] = v.x;
            As[k4 * 4 + 1][r] = v.y;
            As[k4 * 4 + 2][r] = v.z;
            As[k4 * 4 + 3][r] = v.w;
        }
        #pragma unroll
        for (int l = 0; l < 4; l++) {
            int idx = tid + l * 256;
            int kk = idx >> 5, c4 = idx & 31;
            *(float4*)&Ps[kk][c4 * 4] =
                *(const float4*)(Pb + (size_t)(k0 + kk) * ldP + c4 * 4);
        }
        __syncthreads();
        #pragma unroll
        for (int kk = 0; kk < KC; kk++) {
            float4 av = *(float4*)&As[kk][r0];
            float a[4] = {av.x, av.y, av.z, av.w};
            float p[8];
            *(float4*)&p[0] = *(float4*)&Ps[kk][c0];
            *(float4*)&p[4] = *(float4*)&Ps[kk][c0 + 4];
            #pragma unroll
            for (int i = 0; i < 4; i++)
                #pragma unroll
                for (int j = 0; j < 8; j++)
                    acc[i][j] = fmaf(a[i], p[j], acc[i][j]);
        }
        __syncthreads();
    }

    float bv[8];
    #pragma unroll
    for (int j = 0; j < 8; j++) bv[j] = bias[c0 + j];
    float ob = 0.f;
    if (MODE == 3) ob = obsArr[b * TT + tIdx];

    #pragma unroll
    for (int i = 0; i < 4; i++) {
        int row = rowTile + r0 + i;
        size_t base = ((size_t)b * NN + row) * DR;
        #pragma unroll
        for (int j = 0; j < 8; j++) {
            int col = c0 + j;
            float g = acc[i][j] + bv[j];
            size_t idx = base + col;
            if (MODE == 0) {
                dst[idx] = tanhf(g);
            } else if (MODE == 1) {
                dst[idx] = hsrc[idx] + g * DT_VAL;
            } else if (MODE == 2) {
                dst[idx] = 1.f / (1.f + __expf(-g));
            } else {
                float c  = tanhf(g);
                float hv = hsrc[idx];
                dst[idx] = hv + ob * zsrc[idx] * (c - hv);
            }
        }
    }
}

// ---------------- output head: out[b,t-1] = hv1 @ Wo + bo ----------------
__global__ __launch_bounds__(256) void outproj_kernel(
    const float* __restrict__ hv1, const float* __restrict__ Wo,
    const float* __restrict__ bo, float* __restrict__ out, int t)
{
    __shared__ float Hs[KC][68];
    __shared__ float Ws[KC][68];
    int rowTile = blockIdx.x * 64;
    int b  = rowTile >> 10;
    int i0 = rowTile & (NN - 1);
    int tid = threadIdx.x;
    int tx = tid & 7, ty = tid >> 3;   // tx 0..7 cols, ty 0..31 rows
    int c0 = tx * 8,  r0 = ty * 2;

    const float* hb = hv1 + ((size_t)b * NN + i0) * DR;

    float acc[2][8];
    #pragma unroll
    for (int i = 0; i < 2; i++)
        #pragma unroll
        for (int j = 0; j < 8; j++) acc[i][j] = 0.f;

    for (int k0 = 0; k0 < DR; k0 += KC) {
        #pragma unroll
        for (int l = 0; l < 2; l++) {
            int idx = tid + l * 256;
            int r = idx >> 3, k4 = idx & 7;
            float4 v = *(const float4*)(hb + (size_t)r * DR + k0 + k4 * 4);
            Hs[k4 * 4 + 0][r] = v.x;
            Hs[k4 * 4 + 1][r] = v.y;
            Hs[k4 * 4 + 2][r] = v.z;
            Hs[k4 * 4 + 3][r] = v.w;
        }
        #pragma unroll
        for (int l = 0; l < 2; l++) {
            int idx = tid + l * 256;   // 0..511 -> 32 x 16 float4
            int kk = idx >> 4, c4 = idx & 15;
            *(float4*)&Ws[kk][c4 * 4] =
                *(const float4*)(Wo + (size_t)(k0 + kk) * DIN + c4 * 4);
        }
        __syncthreads();
        #pragma unroll
        for (int kk = 0; kk < KC; kk++) {
            float a0 = Hs[kk][r0], a1 = Hs[kk][r0 + 1];
            float p[8];
            *(float4*)&p[0] = *(float4*)&Ws[kk][c0];
            *(float4*)&p[4] = *(float4*)&Ws[kk][c0 + 4];
            #pragma unroll
            for (int j = 0; j < 8; j++) {
                acc[0][j] = fmaf(a0, p[j], acc[0][j]);
                acc[1][j] = fmaf(a1, p[j], acc[1][j]);
            }
        }
        __syncthreads();
    }
    float bv[8];
    #pragma unroll
    for (int j = 0; j < 8; j++) bv[j] = bo[c0 + j];
    float* ob = out + (((size_t)b * (TT - 1) + (t - 1)) * NN + i0) * DIN;
    #pragma unroll
    for (int i = 0; i < 2; i++) {
        float* pr = ob + (size_t)(r0 + i) * DIN + c0;
        *(float4*)(pr + 0) = make_float4(acc[i][0] + bv[0], acc[i][1] + bv[1],
                                         acc[i][2] + bv[2], acc[i][3] + bv[3]);
        *(float4*)(pr + 4) = make_float4(acc[i][4] + bv[4], acc[i][5] + bv[5],
                                         acc[i][6] + bv[6], acc[i][7] + bv[7]);
    }
}

// ---------------- driver ----------------
extern "C" void kernel_launch(void* const* d_in, const int* in_sizes, int n_in,
                              void* d_out, int out_size)
{
    const float* values = (const float*)d_in[0];
    const float* masks  = (const float*)d_in[1];
    const float* A      = (const float*)d_in[2];
    const float* h0     = (const float*)d_in[3];
    const float* W0   = (const float*)d_in[4];
    const float* b0   = (const float*)d_in[5];
    const float* W1   = (const float*)d_in[6];
    const float* b1   = (const float*)d_in[7];
    const float* Wout = (const float*)d_in[8];
    const float* bout = (const float*)d_in[9];
    const float* Wz   = (const float*)d_in[10];
    const float* bz   = (const float*)d_in[11];
    const float* Wr   = (const float*)d_in[12];
    const float* br   = (const float*)d_in[13];
    const float* Wh   = (const float*)d_in[14];
    const float* bh   = (const float*)d_in[15];
    const float* Wo   = (const float*)d_in[16];
    const float* bo   = (const float*)d_in[17];
    float* out = (float*)d_out;

    float *h, *hv1, *u, *P, *z, *r, *obs;
    cudaGetSymbolAddress((void**)&h,   g_h);
    cudaGetSymbolAddress((void**)&hv1, g_hv1);
    cudaGetSymbolAddress((void**)&u,   g_u);
    cudaGetSymbolAddress((void**)&P,   g_P);
    cudaGetSymbolAddress((void**)&z,   g_z);
    cudaGetSymbolAddress((void**)&r,   g_r);
    cudaGetSymbolAddress((void**)&obs, g_obs);

    init_h_kernel<<<256, 256>>>(h0);
    obs_kernel<<<BB * TT, 256>>>(masks);

    dim3 ag(16, 1, 8), ag2(16, 2, 8);

    auto ode_step = [&](const float* hin, float* dst) {
        proj_kernel<false, false><<<128, 256>>>(nullptr, nullptr, 0, hin, nullptr,
                                                W0, 128, P, 128, 0, 128);
        amult_kernel<0><<<ag, 256>>>(A, P, 128, b0, nullptr, u, nullptr,
                                     nullptr, nullptr, nullptr, 0);
        proj_kernel<false, false><<<128, 256>>>(nullptr, nullptr, 0, u, nullptr,
                                                W1, 128, P, 128, 0, 128);
        amult_kernel<0><<<ag, 256>>>(A, P, 128, b1, nullptr, u, nullptr,
                                     nullptr, nullptr, nullptr, 0);
        proj_kernel<false, false><<<128, 256>>>(nullptr, nullptr, 0, u, nullptr,
                                                Wout, 128, P, 128, 0, 128);
        amult_kernel<1><<<ag, 256>>>(A, P, 128, bout, nullptr, dst, nullptr,
                                     hin, nullptr, nullptr, 0);
    };

    // iteration 0: ODE-only update of h
    ode_step(h, h);

    for (int t = 0; t < TT; t++) {
        ode_step(h, hv1);                      // hv1 = h + ode(h)*dt
        // gates z, r on concat([x, hv1]) -> P[:, 0:128] and P[:, 128:256]
        proj_kernel<true, false><<<128, 256>>>(values, masks, t, hv1, nullptr,
                                               Wz, 128, P, 256, 0, 192);
        proj_kernel<true, false><<<128, 256>>>(values, masks, t, hv1, nullptr,
                                               Wr, 128, P, 256, 128, 192);
        amult_kernel<2><<<ag2, 256>>>(A, P, 256, bz, br, z, r,
                                      nullptr, nullptr, nullptr, 0);
        // candidate on concat([x, r*hv1]) then final blend into h
        proj_kernel<true, true><<<128, 256>>>(values, masks, t, hv1, r,
                                              Wh, 128, P, 128, 0, 192);
        amult_kernel<3><<<ag, 256>>>(A, P, 128, bh, nullptr, h, nullptr,
                                     hv1, z, obs, t);
        if (t >= 1)
            outproj_kernel<<<128, 256>>>(hv1, Wo, bo, out, t);
    }
}

// round 2
// speedup vs baseline: 2.3036x; 2.3036x over previous
#include <cuda_runtime.h>
#include <math.h>
#include <stdint.h>

#define BB 8
#define TT 32
#define NN 1024
#define DIN 64
#define DR 128
#define DT_VAL 0.25f
#define KC 32
#define NCHUNK (NN / KC)

// ---------------- device scratch ----------------
__device__ float g_h  [BB * NN * DR];
__device__ float g_hv1[BB * NN * DR];
__device__ float g_u  [BB * NN * DR];
__device__ float g_P  [BB * NN * 256];
__device__ float g_z  [BB * NN * DR];
__device__ float g_r  [BB * NN * DR];
__device__ float g_obs[BB * TT];
__device__ float g_Atf[BB * NN * NN];   // tf32-rounded copy of A (33.5 MB)

// ---------------- helpers ----------------
__device__ __forceinline__ float tf32r(float x) {
    uint32_t u; asm("cvt.rna.tf32.f32 %0, %1;" : "=r"(u) : "f"(x));
    return __uint_as_float(u);
}
__device__ __forceinline__ void cpa16(float* s, const float* g) {
    uint32_t sa = (uint32_t)__cvta_generic_to_shared(s);
    asm volatile("cp.async.cg.shared.global [%0], [%1], 16;" :: "r"(sa), "l"(g));
}

// ---------------- init h = broadcast(h0) ----------------
__global__ void init_h_kernel(const float* __restrict__ h0) {
    int idx = blockIdx.x * blockDim.x + threadIdx.x;
    const int total = BB * NN * DR;
    for (; idx < total; idx += gridDim.x * blockDim.x)
        g_h[idx] = h0[idx & (DR - 1)];
}

// ---------------- round A to tf32 once ----------------
__global__ void round_A_kernel(const float* __restrict__ A) {
    int idx = blockIdx.x * blockDim.x + threadIdx.x;
    const int total = BB * NN * NN;
    for (; idx < total; idx += gridDim.x * blockDim.x)
        g_Atf[idx] = tf32r(A[idx]);
}

// ---------------- obs[b,t] ----------------
__global__ void obs_kernel(const float* __restrict__ masks) {
    int bt = blockIdx.x;
    const float* m = masks + (size_t)bt * NN * DIN;
    float s = 0.f;
    for (int i = threadIdx.x; i < NN * DIN / 4; i += blockDim.x) {
        float4 v = ((const float4*)m)[i];
        s += fabsf(v.x) + fabsf(v.y) + fabsf(v.z) + fabsf(v.w);
    }
    __shared__ float red[256];
    red[threadIdx.x] = s;
    __syncthreads();
    for (int o = 128; o > 0; o >>= 1) {
        if (threadIdx.x < o) red[threadIdx.x] += red[threadIdx.x + o];
        __syncthreads();
    }
    if (threadIdx.x == 0) g_obs[bt] = (red[0] > 1e-4f) ? 1.f : 0.f;
}

// ---------------- projection: P = [x | h or r*h] @ W  (tf32-rounded store) ----
// 32 rows x 128 cols per block, 256 threads, 2x8 micro-tile.
template<bool HAS_X, bool HAS_R>
__global__ __launch_bounds__(256) void proj_kernel(
    const float* __restrict__ xv, const float* __restrict__ xm, int t,
    const float* __restrict__ h,  const float* __restrict__ rr,
    const float* __restrict__ W,  int ldW,
    float* __restrict__ P, int ldP, int colOffP, int Ktot)
{
    __shared__ float Xs[KC][34];    // transposed: Xs[kk][row]
    __shared__ float Ws[KC][132];

    int rowTile = blockIdx.x * 32;
    int b  = rowTile >> 10;
    int i0 = rowTile & (NN - 1);
    int tid = threadIdx.x;
    int tx = tid & 15, ty = tid >> 4;
    int c0 = tx * 8,   r0 = ty * 2;

    const int Kx = HAS_X ? DIN : 0;
    const float* hb  = h + ((size_t)b * NN + i0) * DR;
    const float* rb  = HAS_R ? rr + ((size_t)b * NN + i0) * DR : nullptr;
    const float* xvb = HAS_X ? xv + (((size_t)b * TT + t) * NN + i0) * DIN : nullptr;
    const float* xmb = HAS_X ? xm + (((size_t)b * TT + t) * NN + i0) * DIN : nullptr;

    float acc[2][8];
    #pragma unroll
    for (int i = 0; i < 2; i++)
        #pragma unroll
        for (int j = 0; j < 8; j++) acc[i][j] = 0.f;

    for (int k0 = 0; k0 < Ktot; k0 += KC) {
        // input tile 32 x 32 (transposed), one float4 per thread
        {
            int r = tid >> 3, k4 = tid & 7;
            float4 v;
            if (HAS_X && k0 < DIN) {
                v = *(const float4*)(xvb + (size_t)r * DIN + k0 + k4 * 4);
                float4 mv = *(const float4*)(xmb + (size_t)r * DIN + k0 + k4 * 4);
                v.x *= mv.x; v.y *= mv.y; v.z *= mv.z; v.w *= mv.w;
            } else {
                int kh = k0 - Kx;
                v = *(const float4*)(hb + (size_t)r * DR + kh + k4 * 4);
                if (HAS_R) {
                    float4 rv = *(const float4*)(rb + (size_t)r * DR + kh + k4 * 4);
                    v.x *= rv.x; v.y *= rv.y; v.z *= rv.z; v.w *= rv.w;
                }
            }
            Xs[k4 * 4 + 0][r] = v.x;
            Xs[k4 * 4 + 1][r] = v.y;
            Xs[k4 * 4 + 2][r] = v.z;
            Xs[k4 * 4 + 3][r] = v.w;
        }
        // W tile 32 x 128
        #pragma unroll
        for (int l = 0; l < 4; l++) {
            int idx = tid + l * 256;
            int kk = idx >> 5, c4 = idx & 31;
            *(float4*)&Ws[kk][c4 * 4] =
                *(const float4*)(W + (size_t)(k0 + kk) * ldW + c4 * 4);
        }
        __syncthreads();
        #pragma unroll
        for (int kk = 0; kk < KC; kk++) {
            float2 av = *(float2*)&Xs[kk][r0];
            float a[2] = {av.x, av.y};
            float p[8];
            *(float4*)&p[0] = *(float4*)&Ws[kk][c0];
            *(float4*)&p[4] = *(float4*)&Ws[kk][c0 + 4];
            #pragma unroll
            for (int i = 0; i < 2; i++)
                #pragma unroll
                for (int j = 0; j < 8; j++)
                    acc[i][j] = fmaf(a[i], p[j], acc[i][j]);
        }
        __syncthreads();
    }
    float* Pb = P + ((size_t)b * NN + i0) * ldP + colOffP;
    #pragma unroll
    for (int i = 0; i < 2; i++) {
        float* pr = Pb + (size_t)(r0 + i) * ldP + c0;
        *(float4*)(pr + 0) = make_float4(tf32r(acc[i][0]), tf32r(acc[i][1]),
                                         tf32r(acc[i][2]), tf32r(acc[i][3]));
        *(float4*)(pr + 4) = make_float4(tf32r(acc[i][4]), tf32r(acc[i][5]),
                                         tf32r(acc[i][6]), tf32r(acc[i][7]));
    }
}

// ---------------- tensor-core A-multiply (tf32 mma.sync) -----------------
// G[b,i,c] = sum_j A[b,i,j] * P[b,j,c]; 64x128 tile per CTA, 8 warps (2x4),
// warp tile 32x32 (2 m-frags x 4 n-frags of m16n8k8), cp.async double buffer.
// MODE: 0 tanh, 1 hv1=h+G*dt, 2 sigmoid (grid.y picks z/r), 3 GRU blend.
#define AS_STRIDE 36
#define PS_STRIDE 136
#define AS_BUF (64 * AS_STRIDE)
#define PS_BUF (KC * PS_STRIDE)
#define AMULT_SMEM ((2 * AS_BUF + 2 * PS_BUF) * 4)

template<int MODE>
__global__ __launch_bounds__(256) void amult_tc(
    const float* __restrict__ A,
    const float* __restrict__ P, int ldP,
    const float* __restrict__ bias0, const float* __restrict__ bias1,
    float* __restrict__ dst0, float* __restrict__ dst1,
    const float* __restrict__ hsrc,
    const float* __restrict__ zsrc,
    const float* __restrict__ obsArr, int tIdx)
{
    extern __shared__ float sm[];
    float* AsBase = sm;                 // 2 * 64*36
    float* PsBase = sm + 2 * AS_BUF;    // 2 * 32*136

    const int b = blockIdx.z;
    const int rowTile = blockIdx.x * 64;
    const int cb = blockIdx.y;
    const int colOff = cb * 128;
    const float* bias = (MODE == 2 && cb == 1) ? bias1 : bias0;
    float* dst        = (MODE == 2 && cb == 1) ? dst1  : dst0;

    const int tid  = threadIdx.x;
    const int lane = tid & 31, warp = tid >> 5;
    const int wm = warp & 1, wn = warp >> 1;       // 2 x 4 warp grid
    const int g  = lane >> 2, tig = lane & 3;

    const float* Ab = A + (size_t)b * NN * NN + (size_t)rowTile * NN;
    const float* Pb = P + (size_t)b * NN * ldP + colOff;

    float acc[2][4][4];
    #pragma unroll
    for (int mf = 0; mf < 2; mf++)
        #pragma unroll
        for (int nf = 0; nf < 4; nf++)
            #pragma unroll
            for (int e = 0; e < 4; e++) acc[mf][nf][e] = 0.f;

    auto prefetch = [&](int chunk, int buf) {
        float* Ad = AsBase + buf * AS_BUF;
        float* Pd = PsBase + buf * PS_BUF;
        const float* Ag = Ab + chunk * KC;
        const float* Pg = Pb + (size_t)chunk * KC * ldP;
        #pragma unroll
        for (int l = 0; l < 2; l++) {
            int idx = tid + l * 256;
            int r = idx >> 3, kq = idx & 7;
            cpa16(Ad + r * AS_STRIDE + kq * 4, Ag + (size_t)r * NN + kq * 4);
        }
        #pragma unroll
        for (int l = 0; l < 4; l++) {
            int idx = tid + l * 256;
            int kk = idx >> 5, cq = idx & 31;
            cpa16(Pd + kk * PS_STRIDE + cq * 4, Pg + (size_t)kk * ldP + cq * 4);
        }
        asm volatile("cp.async.commit_group;");
    };

    prefetch(0, 0);
    for (int ch = 0; ch < NCHUNK; ch++) {
        int buf = ch & 1;
        if (ch + 1 < NCHUNK) {
            prefetch(ch + 1, buf ^ 1);
            asm volatile("cp.async.wait_group 1;");
        } else {
            asm volatile("cp.async.wait_group 0;");
        }
        __syncthreads();
        const float* Ad = AsBase + buf * AS_BUF;
        const float* Pd = PsBase + buf * PS_BUF;
        #pragma unroll
        for (int ks = 0; ks < 4; ks++) {
            const int kk = ks * 8;
            uint32_t a[2][4], bf[4][2];
            #pragma unroll
            for (int mf = 0; mf < 2; mf++) {
                int rb = wm * 32 + mf * 16 + g;
                a[mf][0] = __float_as_uint(Ad[(rb)     * AS_STRIDE + kk + tig]);
                a[mf][1] = __float_as_uint(Ad[(rb + 8) * AS_STRIDE + kk + tig]);
                a[mf][2] = __float_as_uint(Ad[(rb)     * AS_STRIDE + kk + tig + 4]);
                a[mf][3] = __float_as_uint(Ad[(rb + 8) * AS_STRIDE + kk + tig + 4]);
            }
            #pragma unroll
            for (int nf = 0; nf < 4; nf++) {
                int nb = wn * 32 + nf * 8 + g;
                bf[nf][0] = __float_as_uint(Pd[(kk + tig)     * PS_STRIDE + nb]);
                bf[nf][1] = __float_as_uint(Pd[(kk + tig + 4) * PS_STRIDE + nb]);
            }
            #pragma unroll
            for (int mf = 0; mf < 2; mf++)
                #pragma unroll
                for (int nf = 0; nf < 4; nf++)
                    asm volatile(
                        "mma.sync.aligned.m16n8k8.row.col.f32.tf32.tf32.f32 "
                        "{%0,%1,%2,%3}, {%4,%5,%6,%7}, {%8,%9}, {%0,%1,%2,%3};"
                        : "+f"(acc[mf][nf][0]), "+f"(acc[mf][nf][1]),
                          "+f"(acc[mf][nf][2]), "+f"(acc[mf][nf][3])
                        : "r"(a[mf][0]), "r"(a[mf][1]), "r"(a[mf][2]), "r"(a[mf][3]),
                          "r"(bf[nf][0]), "r"(bf[nf][1]));
        }
        __syncthreads();
    }

    float ob = (MODE == 3) ? obsArr[b * TT + tIdx] : 0.f;
    #pragma unroll
    for (int mf = 0; mf < 2; mf++) {
        #pragma unroll
        for (int half = 0; half < 2; half++) {
            int row = rowTile + wm * 32 + mf * 16 + g + half * 8;
            size_t base = ((size_t)b * NN + row) * DR;
            #pragma unroll
            for (int nf = 0; nf < 4; nf++) {
                int col = wn * 32 + nf * 8 + 2 * tig;
                float v0 = acc[mf][nf][half * 2 + 0] + bias[col];
                float v1 = acc[mf][nf][half * 2 + 1] + bias[col + 1];
                size_t idx = base + col;
                if (MODE == 0) {
                    v0 = tanhf(v0); v1 = tanhf(v1);
                } else if (MODE == 1) {
                    v0 = hsrc[idx] + v0 * DT_VAL;
                    v1 = hsrc[idx + 1] + v1 * DT_VAL;
                } else if (MODE == 2) {
                    v0 = 1.f / (1.f + __expf(-v0));
                    v1 = 1.f / (1.f + __expf(-v1));
                } else {
                    float c0 = tanhf(v0), c1 = tanhf(v1);
                    float h0v = hsrc[idx], h1v = hsrc[idx + 1];
                    v0 = h0v + ob * zsrc[idx]     * (c0 - h0v);
                    v1 = h1v + ob * zsrc[idx + 1] * (c1 - h1v);
                }
                *(float2*)(dst + idx) = make_float2(v0, v1);
            }
        }
    }
}

// ---------------- output head: out[b,t-1] = hv1 @ Wo + bo ----------------
__global__ __launch_bounds__(256) void outproj_kernel(
    const float* __restrict__ hv1, const float* __restrict__ Wo,
    const float* __restrict__ bo, float* __restrict__ out, int t)
{
    __shared__ float Hs[KC][68];
    __shared__ float Ws[KC][68];
    int rowTile = blockIdx.x * 64;
    int b  = rowTile >> 10;
    int i0 = rowTile & (NN - 1);
    int tid = threadIdx.x;
    int tx = tid & 7, ty = tid >> 3;
    int c0 = tx * 8,  r0 = ty * 2;

    const float* hb = hv1 + ((size_t)b * NN + i0) * DR;

    float acc[2][8];
    #pragma unroll
    for (int i = 0; i < 2; i++)
        #pragma unroll
        for (int j = 0; j < 8; j++) acc[i][j] = 0.f;

    for (int k0 = 0; k0 < DR; k0 += KC) {
        #pragma unroll
        for (int l = 0; l < 2; l++) {
            int idx = tid + l * 256;
            int r = idx >> 3, k4 = idx & 7;
            float4 v = *(const float4*)(hb + (size_t)r * DR + k0 + k4 * 4);
            Hs[k4 * 4 + 0][r] = v.x;
            Hs[k4 * 4 + 1][r] = v.y;
            Hs[k4 * 4 + 2][r] = v.z;
            Hs[k4 * 4 + 3][r] = v.w;
        }
        #pragma unroll
        for (int l = 0; l < 2; l++) {
            int idx = tid + l * 256;
            int kk = idx >> 4, c4 = idx & 15;
            *(float4*)&Ws[kk][c4 * 4] =
                *(const float4*)(Wo + (size_t)(k0 + kk) * DIN + c4 * 4);
        }
        __syncthreads();
        #pragma unroll
        for (int kk = 0; kk < KC; kk++) {
            float a0 = Hs[kk][r0], a1 = Hs[kk][r0 + 1];
            float p[8];
            *(float4*)&p[0] = *(float4*)&Ws[kk][c0];
            *(float4*)&p[4] = *(float4*)&Ws[kk][c0 + 4];
            #pragma unroll
            for (int j = 0; j < 8; j++) {
                acc[0][j] = fmaf(a0, p[j], acc[0][j]);
                acc[1][j] = fmaf(a1, p[j], acc[1][j]);
            }
        }
        __syncthreads();
    }
    float bv[8];
    #pragma unroll
    for (int j = 0; j < 8; j++) bv[j] = bo[c0 + j];
    float* ob = out + (((size_t)b * (TT - 1) + (t - 1)) * NN + i0) * DIN;
    #pragma unroll
    for (int i = 0; i < 2; i++) {
        float* pr = ob + (size_t)(r0 + i) * DIN + c0;
        *(float4*)(pr + 0) = make_float4(acc[i][0] + bv[0], acc[i][1] + bv[1],
                                         acc[i][2] + bv[2], acc[i][3] + bv[3]);
        *(float4*)(pr + 4) = make_float4(acc[i][4] + bv[4], acc[i][5] + bv[5],
                                         acc[i][6] + bv[6], acc[i][7] + bv[7]);
    }
}

// ---------------- driver ----------------
extern "C" void kernel_launch(void* const* d_in, const int* in_sizes, int n_in,
                              void* d_out, int out_size)
{
    const float* values = (const float*)d_in[0];
    const float* masks  = (const float*)d_in[1];
    const float* A      = (const float*)d_in[2];
    const float* h0     = (const float*)d_in[3];
    const float* W0   = (const float*)d_in[4];
    const float* b0   = (const float*)d_in[5];
    const float* W1   = (const float*)d_in[6];
    const float* b1   = (const float*)d_in[7];
    const float* Wout = (const float*)d_in[8];
    const float* bout = (const float*)d_in[9];
    const float* Wz   = (const float*)d_in[10];
    const float* bz   = (const float*)d_in[11];
    const float* Wr   = (const float*)d_in[12];
    const float* br   = (const float*)d_in[13];
    const float* Wh   = (const float*)d_in[14];
    const float* bh   = (const float*)d_in[15];
    const float* Wo   = (const float*)d_in[16];
    const float* bo   = (const float*)d_in[17];
    float* out = (float*)d_out;

    float *h, *hv1, *u, *P, *z, *r, *obs, *Atf;
    cudaGetSymbolAddress((void**)&h,   g_h);
    cudaGetSymbolAddress((void**)&hv1, g_hv1);
    cudaGetSymbolAddress((void**)&u,   g_u);
    cudaGetSymbolAddress((void**)&P,   g_P);
    cudaGetSymbolAddress((void**)&z,   g_z);
    cudaGetSymbolAddress((void**)&r,   g_r);
    cudaGetSymbolAddress((void**)&obs, g_obs);
    cudaGetSymbolAddress((void**)&Atf, g_Atf);

    cudaFuncSetAttribute(amult_tc<0>, cudaFuncAttributeMaxDynamicSharedMemorySize, AMULT_SMEM);
    cudaFuncSetAttribute(amult_tc<1>, cudaFuncAttributeMaxDynamicSharedMemorySize, AMULT_SMEM);
    cudaFuncSetAttribute(amult_tc<2>, cudaFuncAttributeMaxDynamicSharedMemorySize, AMULT_SMEM);
    cudaFuncSetAttribute(amult_tc<3>, cudaFuncAttributeMaxDynamicSharedMemorySize, AMULT_SMEM);

    init_h_kernel<<<256, 256>>>(h0);
    round_A_kernel<<<512, 256>>>(A);
    obs_kernel<<<BB * TT, 256>>>(masks);

    dim3 ag(16, 1, 8), ag2(16, 2, 8);

    auto ode_step = [&](const float* hin, float* dst) {
        proj_kernel<false, false><<<256, 256>>>(nullptr, nullptr, 0, hin, nullptr,
                                                W0, 128, P, 128, 0, 128);
        amult_tc<0><<<ag, 256, AMULT_SMEM>>>(Atf, P, 128, b0, nullptr, u, nullptr,
                                             nullptr, nullptr, nullptr, 0);
        proj_kernel<false, false><<<256, 256>>>(nullptr, nullptr, 0, u, nullptr,
                                                W1, 128, P, 128, 0, 128);
        amult_tc<0><<<ag, 256, AMULT_SMEM>>>(Atf, P, 128, b1, nullptr, u, nullptr,
                                             nullptr, nullptr, nullptr, 0);
        proj_kernel<false, false><<<256, 256>>>(nullptr, nullptr, 0, u, nullptr,
                                                Wout, 128, P, 128, 0, 128);
        amult_tc<1><<<ag, 256, AMULT_SMEM>>>(Atf, P, 128, bout, nullptr, dst, nullptr,
                                             hin, nullptr, nullptr, 0);
    };

    // iteration 0: ODE-only update of h
    ode_step(h, h);

    for (int t = 0; t < TT; t++) {
        ode_step(h, hv1);                      // hv1 = h + ode(h)*dt
        // gates z, r on concat([x, hv1]) -> P[:, 0:128] and P[:, 128:256]
        proj_kernel<true, false><<<256, 256>>>(values, masks, t, hv1, nullptr,
                                               Wz, 128, P, 256, 0, 192);
        proj_kernel<true, false><<<256, 256>>>(values, masks, t, hv1, nullptr,
                                               Wr, 128, P, 256, 128, 192);
        amult_tc<2><<<ag2, 256, AMULT_SMEM>>>(Atf, P, 256, bz, br, z, r,
                                              nullptr, nullptr, nullptr, 0);
        // candidate on concat([x, r*hv1]) then final blend into h
        proj_kernel<true, true><<<256, 256>>>(values, masks, t, hv1, r,
                                              Wh, 128, P, 128, 0, 192);
        amult_tc<3><<<ag, 256, AMULT_SMEM>>>(Atf, P, 128, bh, nullptr, h, nullptr,
                                             hv1, z, obs, t);
        if (t >= 1)
            outproj_kernel<<<128, 256>>>(hv1, Wo, bo, out, t);
    }
}

// round 3
// speedup vs baseline: 3.7859x; 1.6434x over previous
#include <cuda_runtime.h>
#include <math.h>
#include <stdint.h>

#define BB 8
#define TT 32
#define NN 1024
#define DIN 64
#define DR 128
#define DT_VAL 0.25f
#define KC 32
#define NCHUNK (NN / KC)
#define WSLOT (192 * 128)

// ---------------- device scratch ----------------
__device__ float g_h  [BB * NN * DR];
__device__ float g_hv1[BB * NN * DR];
__device__ float g_u  [BB * NN * DR];
__device__ float g_P  [BB * NN * 256];
__device__ float g_z  [BB * NN * DR];
__device__ float g_r  [BB * NN * DR];
__device__ float g_obs[BB * TT];
__device__ float g_Atf[BB * NN * NN];     // tf32-rounded A
__device__ float g_Wtf[6 * WSLOT];        // tf32-rounded weights

// ---------------- helpers ----------------
__device__ __forceinline__ float tf32r(float x) {
    uint32_t u; asm("cvt.rna.tf32.f32 %0, %1;" : "=r"(u) : "f"(x));
    return __uint_as_float(u);
}
__device__ __forceinline__ void cpa16(float* s, const float* g) {
    uint32_t sa = (uint32_t)__cvta_generic_to_shared(s);
    asm volatile("cp.async.cg.shared.global [%0], [%1], 16;" :: "r"(sa), "l"(g));
}

// ---------------- init h = broadcast(h0) ----------------
__global__ void init_h_kernel(const float* __restrict__ h0) {
    int idx = blockIdx.x * blockDim.x + threadIdx.x;
    const int total = BB * NN * DR;
    for (; idx < total; idx += gridDim.x * blockDim.x)
        g_h[idx] = h0[idx & (DR - 1)];
}

// ---------------- round A to tf32 once ----------------
__global__ void round_A_kernel(const float* __restrict__ A) {
    int idx = blockIdx.x * blockDim.x + threadIdx.x;
    const int total = BB * NN * NN;
    for (; idx < total; idx += gridDim.x * blockDim.x)
        g_Atf[idx] = tf32r(A[idx]);
}

// ---------------- round weights to tf32 once ----------------
// slots: 0 W0(128x128) 1 W1(128x128) 2 Wout(128x128) 3 Wz(192x128) 4 Wr 5 Wh
__global__ void round_W_kernel(
    const float* __restrict__ W0, const float* __restrict__ W1,
    const float* __restrict__ Wout, const float* __restrict__ Wz,
    const float* __restrict__ Wr, const float* __restrict__ Wh)
{
    const float* srcs[6] = {W0, W1, Wout, Wz, Wr, Wh};
    const int sizes[6] = {128*128, 128*128, 128*128, 192*128, 192*128, 192*128};
    for (int s = 0; s < 6; s++) {
        const float* src = srcs[s];
        float* dst = g_Wtf + s * WSLOT;
        for (int i = blockIdx.x * blockDim.x + threadIdx.x; i < sizes[s];
             i += gridDim.x * blockDim.x)
            dst[i] = tf32r(src[i]);
    }
}

// ---------------- obs[b,t] ----------------
__global__ void obs_kernel(const float* __restrict__ masks) {
    int bt = blockIdx.x;
    const float* m = masks + (size_t)bt * NN * DIN;
    float s = 0.f;
    for (int i = threadIdx.x; i < NN * DIN / 4; i += blockDim.x) {
        float4 v = ((const float4*)m)[i];
        s += fabsf(v.x) + fabsf(v.y) + fabsf(v.z) + fabsf(v.w);
    }
    __shared__ float red[256];
    red[threadIdx.x] = s;
    __syncthreads();
    for (int o = 128; o > 0; o >>= 1) {
        if (threadIdx.x < o) red[threadIdx.x] += red[threadIdx.x + o];
        __syncthreads();
    }
    if (threadIdx.x == 0) g_obs[bt] = (red[0] > 1e-4f) ? 1.f : 0.f;
}

// ---------------- tensor-core projection -----------------
// P[:, colOff:colOff+128] = tf32( [x*m | h or r*h] @ W )
// 64 rows x 128 cols per CTA; 8 warps 2x4; warp tile 32x32.
// grid.y selects (Wa, colOff=0) or (Wb, colOff=128).
#define XS_STRIDE 36
#define WS_STRIDE 136

template<bool HAS_X, bool HAS_R>
__global__ __launch_bounds__(256) void proj_tc(
    const float* __restrict__ xv, const float* __restrict__ xm, int t,
    const float* __restrict__ h,  const float* __restrict__ rr,
    const float* __restrict__ Wa, const float* __restrict__ Wb,
    float* __restrict__ P, int ldP, int Ktot)
{
    __shared__ float Xs[64 * XS_STRIDE];
    __shared__ float Ws[KC * WS_STRIDE];

    const int rowTile = blockIdx.x * 64;
    const int b  = rowTile >> 10;
    const int i0 = rowTile & (NN - 1);
    const int colOff = blockIdx.y * 128;
    const float* W = blockIdx.y ? Wb : Wa;

    const int tid  = threadIdx.x;
    const int lane = tid & 31, warp = tid >> 5;
    const int wm = warp & 1, wn = warp >> 1;
    const int g  = lane >> 2, tig = lane & 3;

    const int Kx = HAS_X ? DIN : 0;
    const float* hb  = h + ((size_t)b * NN + i0) * DR;
    const float* rb  = HAS_R ? rr + ((size_t)b * NN + i0) * DR : nullptr;
    const float* xvb = HAS_X ? xv + (((size_t)b * TT + t) * NN + i0) * DIN : nullptr;
    const float* xmb = HAS_X ? xm + (((size_t)b * TT + t) * NN + i0) * DIN : nullptr;

    float acc[2][4][4];
    #pragma unroll
    for (int mf = 0; mf < 2; mf++)
        #pragma unroll
        for (int nf = 0; nf < 4; nf++)
            #pragma unroll
            for (int e = 0; e < 4; e++) acc[mf][nf][e] = 0.f;

    for (int k0 = 0; k0 < Ktot; k0 += KC) {
        // activation tile 64 x 32 (row-major, stride 36), fused elementwise + cvt
        #pragma unroll
        for (int l = 0; l < 2; l++) {
            int idx = tid + l * 256;
            int r = idx >> 3, k4 = idx & 7;
            float4 v;
            if (HAS_X && k0 < DIN) {
                v = *(const float4*)(xvb + (size_t)r * DIN + k0 + k4 * 4);
                float4 mv = *(const float4*)(xmb + (size_t)r * DIN + k0 + k4 * 4);
                v.x *= mv.x; v.y *= mv.y; v.z *= mv.z; v.w *= mv.w;
            } else {
                int kh = k0 - Kx;
                v = *(const float4*)(hb + (size_t)r * DR + kh + k4 * 4);
                if (HAS_R) {
                    float4 rv = *(const float4*)(rb + (size_t)r * DR + kh + k4 * 4);
                    v.x *= rv.x; v.y *= rv.y; v.z *= rv.z; v.w *= rv.w;
                }
            }
            v.x = tf32r(v.x); v.y = tf32r(v.y); v.z = tf32r(v.z); v.w = tf32r(v.w);
            *(float4*)&Xs[r * XS_STRIDE + k4 * 4] = v;
        }
        // W tile 32 x 128 (pre-rounded)
        #pragma unroll
        for (int l = 0; l < 4; l++) {
            int idx = tid + l * 256;
            int kk = idx >> 5, c4 = idx & 31;
            *(float4*)&Ws[kk * WS_STRIDE + c4 * 4] =
                *(const float4*)(W + (size_t)(k0 + kk) * 128 + c4 * 4);
        }
        __syncthreads();
        #pragma unroll
        for (int ks = 0; ks < 4; ks++) {
            const int kk = ks * 8;
            uint32_t a[2][4], bf[4][2];
            #pragma unroll
            for (int mf = 0; mf < 2; mf++) {
                int rbase = wm * 32 + mf * 16 + g;
                a[mf][0] = __float_as_uint(Xs[(rbase)     * XS_STRIDE + kk + tig]);
                a[mf][1] = __float_as_uint(Xs[(rbase + 8) * XS_STRIDE + kk + tig]);
                a[mf][2] = __float_as_uint(Xs[(rbase)     * XS_STRIDE + kk + tig + 4]);
                a[mf][3] = __float_as_uint(Xs[(rbase + 8) * XS_STRIDE + kk + tig + 4]);
            }
            #pragma unroll
            for (int nf = 0; nf < 4; nf++) {
                int nb = wn * 32 + nf * 8 + g;
                bf[nf][0] = __float_as_uint(Ws[(kk + tig)     * WS_STRIDE + nb]);
                bf[nf][1] = __float_as_uint(Ws[(kk + tig + 4) * WS_STRIDE + nb]);
            }
            #pragma unroll
            for (int mf = 0; mf < 2; mf++)
                #pragma unroll
                for (int nf = 0; nf < 4; nf++)
                    asm volatile(
                        "mma.sync.aligned.m16n8k8.row.col.f32.tf32.tf32.f32 "
                        "{%0,%1,%2,%3}, {%4,%5,%6,%7}, {%8,%9}, {%0,%1,%2,%3};"
                        : "+f"(acc[mf][nf][0]), "+f"(acc[mf][nf][1]),
                          "+f"(acc[mf][nf][2]), "+f"(acc[mf][nf][3])
                        : "r"(a[mf][0]), "r"(a[mf][1]), "r"(a[mf][2]), "r"(a[mf][3]),
                          "r"(bf[nf][0]), "r"(bf[nf][1]));
        }
        __syncthreads();
    }

    float* Pb = P + ((size_t)b * NN + i0) * ldP + colOff;
    #pragma unroll
    for (int mf = 0; mf < 2; mf++) {
        #pragma unroll
        for (int half = 0; half < 2; half++) {
            int row = wm * 32 + mf * 16 + g + half * 8;
            #pragma unroll
            for (int nf = 0; nf < 4; nf++) {
                int col = wn * 32 + nf * 8 + 2 * tig;
                float v0 = tf32r(acc[mf][nf][half * 2 + 0]);
                float v1 = tf32r(acc[mf][nf][half * 2 + 1]);
                *(float2*)(Pb + (size_t)row * ldP + col) = make_float2(v0, v1);
            }
        }
    }
}

// ---------------- tensor-core A-multiply (tf32 mma.sync) -----------------
#define AS_STRIDE 36
#define PS_STRIDE 136
#define AS_BUF (64 * AS_STRIDE)
#define PS_BUF (KC * PS_STRIDE)
#define AMULT_SMEM ((2 * AS_BUF + 2 * PS_BUF) * 4)

template<int MODE>
__global__ __launch_bounds__(256) void amult_tc(
    const float* __restrict__ A,
    const float* __restrict__ P, int ldP,
    const float* __restrict__ bias0, const float* __restrict__ bias1,
    float* __restrict__ dst0, float* __restrict__ dst1,
    const float* __restrict__ hsrc,
    const float* __restrict__ zsrc,
    const float* __restrict__ obsArr, int tIdx)
{
    extern __shared__ float sm[];
    float* AsBase = sm;
    float* PsBase = sm + 2 * AS_BUF;

    const int b = blockIdx.z;
    const int rowTile = blockIdx.x * 64;
    const int cb = blockIdx.y;
    const int colOff = cb * 128;
    const float* bias = (MODE == 2 && cb == 1) ? bias1 : bias0;
    float* dst        = (MODE == 2 && cb == 1) ? dst1  : dst0;

    const int tid  = threadIdx.x;
    const int lane = tid & 31, warp = tid >> 5;
    const int wm = warp & 1, wn = warp >> 1;
    const int g  = lane >> 2, tig = lane & 3;

    const float* Ab = A + (size_t)b * NN * NN + (size_t)rowTile * NN;
    const float* Pb = P + (size_t)b * NN * ldP + colOff;

    float acc[2][4][4];
    #pragma unroll
    for (int mf = 0; mf < 2; mf++)
        #pragma unroll
        for (int nf = 0; nf < 4; nf++)
            #pragma unroll
            for (int e = 0; e < 4; e++) acc[mf][nf][e] = 0.f;

    auto prefetch = [&](int chunk, int buf) {
        float* Ad = AsBase + buf * AS_BUF;
        float* Pd = PsBase + buf * PS_BUF;
        const float* Ag = Ab + chunk * KC;
        const float* Pg = Pb + (size_t)chunk * KC * ldP;
        #pragma unroll
        for (int l = 0; l < 2; l++) {
            int idx = tid + l * 256;
            int r = idx >> 3, kq = idx & 7;
            cpa16(Ad + r * AS_STRIDE + kq * 4, Ag + (size_t)r * NN + kq * 4);
        }
        #pragma unroll
        for (int l = 0; l < 4; l++) {
            int idx = tid + l * 256;
            int kk = idx >> 5, cq = idx & 31;
            cpa16(Pd + kk * PS_STRIDE + cq * 4, Pg + (size_t)kk * ldP + cq * 4);
        }
        asm volatile("cp.async.commit_group;");
    };

    prefetch(0, 0);
    for (int ch = 0; ch < NCHUNK; ch++) {
        int buf = ch & 1;
        if (ch + 1 < NCHUNK) {
            prefetch(ch + 1, buf ^ 1);
            asm volatile("cp.async.wait_group 1;");
        } else {
            asm volatile("cp.async.wait_group 0;");
        }
        __syncthreads();
        const float* Ad = AsBase + buf * AS_BUF;
        const float* Pd = PsBase + buf * PS_BUF;
        #pragma unroll
        for (int ks = 0; ks < 4; ks++) {
            const int kk = ks * 8;
            uint32_t a[2][4], bf[4][2];
            #pragma unroll
            for (int mf = 0; mf < 2; mf++) {
                int rb = wm * 32 + mf * 16 + g;
                a[mf][0] = __float_as_uint(Ad[(rb)     * AS_STRIDE + kk + tig]);
                a[mf][1] = __float_as_uint(Ad[(rb + 8) * AS_STRIDE + kk + tig]);
                a[mf][2] = __float_as_uint(Ad[(rb)     * AS_STRIDE + kk + tig + 4]);
                a[mf][3] = __float_as_uint(Ad[(rb + 8) * AS_STRIDE + kk + tig + 4]);
            }
            #pragma unroll
            for (int nf = 0; nf < 4; nf++) {
                int nb = wn * 32 + nf * 8 + g;
                bf[nf][0] = __float_as_uint(Pd[(kk + tig)     * PS_STRIDE + nb]);
                bf[nf][1] = __float_as_uint(Pd[(kk + tig + 4) * PS_STRIDE + nb]);
            }
            #pragma unroll
            for (int mf = 0; mf < 2; mf++)
                #pragma unroll
                for (int nf = 0; nf < 4; nf++)
                    asm volatile(
                        "mma.sync.aligned.m16n8k8.row.col.f32.tf32.tf32.f32 "
                        "{%0,%1,%2,%3}, {%4,%5,%6,%7}, {%8,%9}, {%0,%1,%2,%3};"
                        : "+f"(acc[mf][nf][0]), "+f"(acc[mf][nf][1]),
                          "+f"(acc[mf][nf][2]), "+f"(acc[mf][nf][3])
                        : "r"(a[mf][0]), "r"(a[mf][1]), "r"(a[mf][2]), "r"(a[mf][3]),
                          "r"(bf[nf][0]), "r"(bf[nf][1]));
        }
        __syncthreads();
    }

    float ob = (MODE == 3) ? obsArr[b * TT + tIdx] : 0.f;
    #pragma unroll
    for (int mf = 0; mf < 2; mf++) {
        #pragma unroll
        for (int half = 0; half < 2; half++) {
            int row = rowTile + wm * 32 + mf * 16 + g + half * 8;
            size_t base = ((size_t)b * NN + row) * DR;
            #pragma unroll
            for (int nf = 0; nf < 4; nf++) {
                int col = wn * 32 + nf * 8 + 2 * tig;
                float v0 = acc[mf][nf][half * 2 + 0] + bias[col];
                float v1 = acc[mf][nf][half * 2 + 1] + bias[col + 1];
                size_t idx = base + col;
                if (MODE == 0) {
                    v0 = tanhf(v0); v1 = tanhf(v1);
                } else if (MODE == 1) {
                    v0 = hsrc[idx] + v0 * DT_VAL;
                    v1 = hsrc[idx + 1] + v1 * DT_VAL;
                } else if (MODE == 2) {
                    v0 = 1.f / (1.f + __expf(-v0));
                    v1 = 1.f / (1.f + __expf(-v1));
                } else {
                    float c0 = tanhf(v0), c1 = tanhf(v1);
                    float h0v = hsrc[idx], h1v = hsrc[idx + 1];
                    v0 = h0v + ob * zsrc[idx]     * (c0 - h0v);
                    v1 = h1v + ob * zsrc[idx + 1] * (c1 - h1v);
                }
                *(float2*)(dst + idx) = make_float2(v0, v1);
            }
        }
    }
}

// ---------------- output head: out[b,t-1] = hv1 @ Wo + bo (fp32) ----------
__global__ __launch_bounds__(256) void outproj_kernel(
    const float* __restrict__ hv1, const float* __restrict__ Wo,
    const float* __restrict__ bo, float* __restrict__ out, int t)
{
    __shared__ float Hs[KC][68];
    __shared__ float Ws[KC][68];
    int rowTile = blockIdx.x * 64;
    int b  = rowTile >> 10;
    int i0 = rowTile & (NN - 1);
    int tid = threadIdx.x;
    int tx = tid & 7, ty = tid >> 3;
    int c0 = tx * 8,  r0 = ty * 2;

    const float* hb = hv1 + ((size_t)b * NN + i0) * DR;

    float acc[2][8];
    #pragma unroll
    for (int i = 0; i < 2; i++)
        #pragma unroll
        for (int j = 0; j < 8; j++) acc[i][j] = 0.f;

    for (int k0 = 0; k0 < DR; k0 += KC) {
        #pragma unroll
        for (int l = 0; l < 2; l++) {
            int idx = tid + l * 256;
            int r = idx >> 3, k4 = idx & 7;
            float4 v = *(const float4*)(hb + (size_t)r * DR + k0 + k4 * 4);
            Hs[k4 * 4 + 0][r] = v.x;
            Hs[k4 * 4 + 1][r] = v.y;
            Hs[k4 * 4 + 2][r] = v.z;
            Hs[k4 * 4 + 3][r] = v.w;
        }
        #pragma unroll
        for (int l = 0; l < 2; l++) {
            int idx = tid + l * 256;
            int kk = idx >> 4, c4 = idx & 15;
            *(float4*)&Ws[kk][c4 * 4] =
                *(const float4*)(Wo + (size_t)(k0 + kk) * DIN + c4 * 4);
        }
        __syncthreads();
        #pragma unroll
        for (int kk = 0; kk < KC; kk++) {
            float a0 = Hs[kk][r0], a1 = Hs[kk][r0 + 1];
            float p[8];
            *(float4*)&p[0] = *(float4*)&Ws[kk][c0];
            *(float4*)&p[4] = *(float4*)&Ws[kk][c0 + 4];
            #pragma unroll
            for (int j = 0; j < 8; j++) {
                acc[0][j] = fmaf(a0, p[j], acc[0][j]);
                acc[1][j] = fmaf(a1, p[j], acc[1][j]);
            }
        }
        __syncthreads();
    }
    float bv[8];
    #pragma unroll
    for (int j = 0; j < 8; j++) bv[j] = bo[c0 + j];
    float* ob = out + (((size_t)b * (TT - 1) + (t - 1)) * NN + i0) * DIN;
    #pragma unroll
    for (int i = 0; i < 2; i++) {
        float* pr = ob + (size_t)(r0 + i) * DIN + c0;
        *(float4*)(pr + 0) = make_float4(acc[i][0] + bv[0], acc[i][1] + bv[1],
                                         acc[i][2] + bv[2], acc[i][3] + bv[3]);
        *(float4*)(pr + 4) = make_float4(acc[i][4] + bv[4], acc[i][5] + bv[5],
                                         acc[i][6] + bv[6], acc[i][7] + bv[7]);
    }
}

// ---------------- driver ----------------
extern "C" void kernel_launch(void* const* d_in, const int* in_sizes, int n_in,
                              void* d_out, int out_size)
{
    const float* values = (const float*)d_in[0];
    const float* masks  = (const float*)d_in[1];
    const float* A      = (const float*)d_in[2];
    const float* h0     = (const float*)d_in[3];
    const float* W0   = (const float*)d_in[4];
    const float* b0   = (const float*)d_in[5];
    const float* W1   = (const float*)d_in[6];
    const float* b1   = (const float*)d_in[7];
    const float* Wout = (const float*)d_in[8];
    const float* bout = (const float*)d_in[9];
    const float* Wz   = (const float*)d_in[10];
    const float* bz   = (const float*)d_in[11];
    const float* Wr   = (const float*)d_in[12];
    const float* br   = (const float*)d_in[13];
    const float* Wh   = (const float*)d_in[14];
    const float* bh   = (const float*)d_in[15];
    const float* Wo   = (const float*)d_in[16];
    const float* bo   = (const float*)d_in[17];
    float* out = (float*)d_out;

    float *h, *hv1, *u, *P, *z, *r, *obs, *Atf, *Wtf;
    cudaGetSymbolAddress((void**)&h,   g_h);
    cudaGetSymbolAddress((void**)&hv1, g_hv1);
    cudaGetSymbolAddress((void**)&u,   g_u);
    cudaGetSymbolAddress((void**)&P,   g_P);
    cudaGetSymbolAddress((void**)&z,   g_z);
    cudaGetSymbolAddress((void**)&r,   g_r);
    cudaGetSymbolAddress((void**)&obs, g_obs);
    cudaGetSymbolAddress((void**)&Atf, g_Atf);
    cudaGetSymbolAddress((void**)&Wtf, g_Wtf);

    cudaFuncSetAttribute(amult_tc<0>, cudaFuncAttributeMaxDynamicSharedMemorySize, AMULT_SMEM);
    cudaFuncSetAttribute(amult_tc<1>, cudaFuncAttributeMaxDynamicSharedMemorySize, AMULT_SMEM);
    cudaFuncSetAttribute(amult_tc<2>, cudaFuncAttributeMaxDynamicSharedMemorySize, AMULT_SMEM);
    cudaFuncSetAttribute(amult_tc<3>, cudaFuncAttributeMaxDynamicSharedMemorySize, AMULT_SMEM);

    init_h_kernel<<<256, 256>>>(h0);
    round_A_kernel<<<512, 256>>>(A);
    round_W_kernel<<<128, 256>>>(W0, W1, Wout, Wz, Wr, Wh);
    obs_kernel<<<BB * TT, 256>>>(masks);

    const float* tW0   = Wtf + 0 * WSLOT;
    const float* tW1   = Wtf + 1 * WSLOT;
    const float* tWout = Wtf + 2 * WSLOT;
    const float* tWz   = Wtf + 3 * WSLOT;
    const float* tWr   = Wtf + 4 * WSLOT;
    const float* tWh   = Wtf + 5 * WSLOT;

    dim3 ag(16, 1, 8), ag2(16, 2, 8);
    dim3 pg(128, 1, 1), pg2(128, 2, 1);

    auto ode_step = [&](const float* hin, float* dst) {
        proj_tc<false, false><<<pg, 256>>>(nullptr, nullptr, 0, hin, nullptr,
                                           tW0, nullptr, P, 128, 128);
        amult_tc<0><<<ag, 256, AMULT_SMEM>>>(Atf, P, 128, b0, nullptr, u, nullptr,
                                             nullptr, nullptr, nullptr, 0);
        proj_tc<false, false><<<pg, 256>>>(nullptr, nullptr, 0, u, nullptr,
                                           tW1, nullptr, P, 128, 128);
        amult_tc<0><<<ag, 256, AMULT_SMEM>>>(Atf, P, 128, b1, nullptr, u, nullptr,
                                             nullptr, nullptr, nullptr, 0);
        proj_tc<false, false><<<pg, 256>>>(nullptr, nullptr, 0, u, nullptr,
                                           tWout, nullptr, P, 128, 128);
        amult_tc<1><<<ag, 256, AMULT_SMEM>>>(Atf, P, 128, bout, nullptr, dst, nullptr,
                                             hin, nullptr, nullptr, 0);
    };

    // iteration 0: ODE-only update of h
    ode_step(h, h);

    for (int t = 0; t < TT; t++) {
        ode_step(h, hv1);                      // hv1 = h + ode(h)*dt
        // gates z, r on concat([x, hv1]); one launch, grid.y picks Wz/Wr
        proj_tc<true, false><<<pg2, 256>>>(values, masks, t, hv1, nullptr,
                                           tWz, tWr, P, 256, 192);
        amult_tc<2><<<ag2, 256, AMULT_SMEM>>>(Atf, P, 256, bz, br, z, r,
                                              nullptr, nullptr, nullptr, 0);
        // candidate on concat([x, r*hv1]) then final blend into h
        proj_tc<true, true><<<pg, 256>>>(values, masks, t, hv1, r,
                                         tWh, nullptr, P, 128, 192);
        amult_tc<3><<<ag, 256, AMULT_SMEM>>>(Atf, P, 128, bh, nullptr, h, nullptr,
                                             hv1, z, obs, t);
        if (t >= 1)
            outproj_kernel<<<128, 256>>>(hv1, Wo, bo, out, t);
    }
}